// round 2
// baseline (speedup 1.0000x reference)
#include <cuda_runtime.h>
#include <math.h>

// B=8, N=1024, C=768, H=12, D=64, level=8, thresh=1.0, scale=0.125
// Scratch (device globals — no allocation allowed):
__device__ __align__(16) signed char g_q[8 * 12 * 1024 * 64];
__device__ __align__(16) signed char g_k[8 * 12 * 1024 * 64];
__device__ __align__(16) signed char g_v[8 * 12 * 1024 * 64];
__device__ __align__(16) signed char g_t[8192 * 768];

__device__ __forceinline__ int tern_of(float v) {
    // faithful to reference: u = x/1.0 + 0.5 ; pos iff u>=1 ; neg iff u<0
    const float u = v + 0.5f;
    return (u >= 1.0f) ? 1 : ((u < 0.0f) ? -1 : 0);
}

// ---------------------------------------------------------------------------
// GEMM1: QKV[m, o] = sum_c X[m,c] * Wqkv[o,c]  (M=8192, N=2304, K=768, fp32)
// Epilogue: ternarize and scatter into g_q/g_k/g_v with [b,h,n,d] layout.
// 128x128 block tile, 8x8 per thread, BK=8, smem double-buffered.
// ---------------------------------------------------------------------------
__global__ void __launch_bounds__(256) gemm_qkv_kernel(const float* __restrict__ X,
                                                       const float* __restrict__ W) {
    __shared__ float As[2][8][132];
    __shared__ float Bs[2][8][132];
    const int tid = threadIdx.x;
    const int tx = tid & 15, ty = tid >> 4;
    const int rowBase = blockIdx.y * 128;
    const int colBase = blockIdx.x * 128;
    const int lr = tid >> 1;          // 0..127
    const int lk = (tid & 1) * 4;     // 0 or 4

    const float* Ag = X + (size_t)(rowBase + lr) * 768 + lk;
    const float* Bg = W + (size_t)(colBase + lr) * 768 + lk;

    float acc[8][8];
#pragma unroll
    for (int i = 0; i < 8; i++)
#pragma unroll
        for (int j = 0; j < 8; j++) acc[i][j] = 0.0f;

    {
        const float4 a4 = *(const float4*)Ag;
        const float4 b4 = *(const float4*)Bg;
        As[0][lk + 0][lr] = a4.x; As[0][lk + 1][lr] = a4.y;
        As[0][lk + 2][lr] = a4.z; As[0][lk + 3][lr] = a4.w;
        Bs[0][lk + 0][lr] = b4.x; Bs[0][lk + 1][lr] = b4.y;
        Bs[0][lk + 2][lr] = b4.z; Bs[0][lk + 3][lr] = b4.w;
    }
    __syncthreads();

    int buf = 0;
    for (int kt = 0; kt < 768; kt += 8) {
        float4 na, nb;
        const bool nxt = (kt + 8) < 768;
        if (nxt) {
            na = *(const float4*)(Ag + kt + 8);
            nb = *(const float4*)(Bg + kt + 8);
        }
#pragma unroll
        for (int kk = 0; kk < 8; kk++) {
            float a[8], b[8];
            *(float4*)(a)     = *(const float4*)&As[buf][kk][ty * 8];
            *(float4*)(a + 4) = *(const float4*)&As[buf][kk][ty * 8 + 4];
            *(float4*)(b)     = *(const float4*)&Bs[buf][kk][tx * 8];
            *(float4*)(b + 4) = *(const float4*)&Bs[buf][kk][tx * 8 + 4];
#pragma unroll
            for (int i = 0; i < 8; i++)
#pragma unroll
                for (int j = 0; j < 8; j++) acc[i][j] = fmaf(a[i], b[j], acc[i][j]);
        }
        if (nxt) {
            const int nb2 = buf ^ 1;
            As[nb2][lk + 0][lr] = na.x; As[nb2][lk + 1][lr] = na.y;
            As[nb2][lk + 2][lr] = na.z; As[nb2][lk + 3][lr] = na.w;
            Bs[nb2][lk + 0][lr] = nb.x; Bs[nb2][lk + 1][lr] = nb.y;
            Bs[nb2][lk + 2][lr] = nb.z; Bs[nb2][lk + 3][lr] = nb.w;
        }
        __syncthreads();
        buf ^= 1;
    }

    // Epilogue: section boundaries (768) are multiples of 128, so the whole
    // block lies in one of q/k/v, and each thread's 8 cols stay in one head.
    const int sec = colBase / 768;  // 0=q, 1=k, 2=v
    signed char* dst = (sec == 0) ? g_q : ((sec == 1) ? g_k : g_v);
    const int cc = colBase - sec * 768 + tx * 8;
    const int h = cc >> 6;
    const int d0 = cc & 63;
#pragma unroll
    for (int i = 0; i < 8; i++) {
        const int row = rowBase + ty * 8 + i;
        const int bb = row >> 10;
        const int nn = row & 1023;
        unsigned lo = 0, hi = 0;
#pragma unroll
        for (int j = 0; j < 4; j++) {
            lo |= ((unsigned)(tern_of(acc[i][j])     & 0xFF)) << (8 * j);
            hi |= ((unsigned)(tern_of(acc[i][j + 4]) & 0xFF)) << (8 * j);
        }
        uint2* p = (uint2*)(dst + ((size_t)((bb * 12 + h) * 1024 + nn) * 64 + d0));
        *p = make_uint2(lo, hi);
    }
}

// ---------------------------------------------------------------------------
// Attention kernel. One block per (b,h) x 64-row slab.
// K tile packed as int32 words in smem (transposed [16][1024] for conflict-free
// reads). Each warp processes 2 q-rows per pass (shares K reads).
// s = 0.125 * dp4a-dot ; softmax(max, Z) ; spike iff (p + 0.5) >= 1 ;
// out = sum of spiking V rows (rare — ballot + sparse gather) ; ternarize.
// ---------------------------------------------------------------------------
__global__ void __launch_bounds__(256) attn_kernel() {
    extern __shared__ int smem_dyn[];
    int* Kp = smem_dyn;                         // [16][1024] int32 = 64KB
    float* sbuf = (float*)(smem_dyn + 16384);   // [8 warps][2][1024] = 64KB

    const int bh = blockIdx.x;          // 0..95
    const int bb = bh / 12, h = bh % 12;
    const int tid = threadIdx.x;
    const int lane = tid & 31, warp = tid >> 5;

    const signed char* kbase = g_k + (size_t)bh * 65536;
    const signed char* vbase = g_v + (size_t)bh * 65536;
    const signed char* qbase = g_q + (size_t)bh * 65536;

    // Load K (1024x64 int8) into smem transposed: Kp[w][m], w = word index 0..15
    for (int flat = tid; flat < 4096; flat += 256) {
        const int m = flat >> 2, wg = flat & 3;
        const int4 kv = *(const int4*)(kbase + m * 64 + wg * 16);
        Kp[(wg * 4 + 0) * 1024 + m] = kv.x;
        Kp[(wg * 4 + 1) * 1024 + m] = kv.y;
        Kp[(wg * 4 + 2) * 1024 + m] = kv.z;
        Kp[(wg * 4 + 3) * 1024 + m] = kv.w;
    }
    __syncthreads();

    float* sb0 = sbuf + warp * 2048;
    float* sb1 = sb0 + 1024;
    const int rowBase = blockIdx.y * 64;

    for (int pass = 0; pass < 4; pass++) {
        const int r0 = rowBase + pass * 16 + warp * 2;
        const int r1 = r0 + 1;

        int q0[16], q1[16];
        {
            const int4* qp = (const int4*)(qbase + (size_t)r0 * 64);
#pragma unroll
            for (int w = 0; w < 4; w++) {
                const int4 t0 = qp[w];
                q0[w * 4 + 0] = t0.x; q0[w * 4 + 1] = t0.y;
                q0[w * 4 + 2] = t0.z; q0[w * 4 + 3] = t0.w;
                const int4 t1 = qp[4 + w];  // row r1 = r0+1 (64B = 4 int4)
                q1[w * 4 + 0] = t1.x; q1[w * 4 + 1] = t1.y;
                q1[w * 4 + 2] = t1.z; q1[w * 4 + 3] = t1.w;
            }
        }

        // Pass 1: logits + row max
        float mx0 = -1e30f, mx1 = -1e30f;
        for (int m = lane; m < 1024; m += 32) {
            int a0 = 0, a1 = 0;
#pragma unroll
            for (int w = 0; w < 16; w++) {
                const int kv = Kp[w * 1024 + m];
                a0 = __dp4a(q0[w], kv, a0);
                a1 = __dp4a(q1[w], kv, a1);
            }
            const float s0 = 0.125f * (float)a0;
            const float s1 = 0.125f * (float)a1;
            sb0[m] = s0; sb1[m] = s1;
            mx0 = fmaxf(mx0, s0); mx1 = fmaxf(mx1, s1);
        }
#pragma unroll
        for (int off = 16; off; off >>= 1) {
            mx0 = fmaxf(mx0, __shfl_xor_sync(0xffffffffu, mx0, off));
            mx1 = fmaxf(mx1, __shfl_xor_sync(0xffffffffu, mx1, off));
        }

        // Pass 2: exp + Z
        float Z0 = 0.0f, Z1 = 0.0f;
        for (int m = lane; m < 1024; m += 32) {
            const float e0 = expf(sb0[m] - mx0);
            const float e1 = expf(sb1[m] - mx1);
            sb0[m] = e0; sb1[m] = e1;
            Z0 += e0; Z1 += e1;
        }
#pragma unroll
        for (int off = 16; off; off >>= 1) {
            Z0 += __shfl_xor_sync(0xffffffffu, Z0, off);
            Z1 += __shfl_xor_sync(0xffffffffu, Z1, off);
        }

        // Pass 3: spike detection + sparse V gather.
        // Lane owns output dims 2*lane and 2*lane+1.
        int a00 = 0, a01 = 0, a10 = 0, a11 = 0;
        for (int mb = 0; mb < 1024; mb += 32) {
            const int m = mb + lane;
            const float p0 = sb0[m] / Z0;
            const float p1 = sb1[m] / Z1;
            unsigned bal0 = __ballot_sync(0xffffffffu, (p0 + 0.5f) >= 1.0f);
            unsigned bal1 = __ballot_sync(0xffffffffu, (p1 + 0.5f) >= 1.0f);
            while (bal0) {
                const int bit = __ffs(bal0) - 1; bal0 &= bal0 - 1;
                const char2 vv = *(const char2*)(vbase + (size_t)(mb + bit) * 64 + 2 * lane);
                a00 += vv.x; a01 += vv.y;
            }
            while (bal1) {
                const int bit = __ffs(bal1) - 1; bal1 &= bal1 - 1;
                const char2 vv = *(const char2*)(vbase + (size_t)(mb + bit) * 64 + 2 * lane);
                a10 += vv.x; a11 += vv.y;
            }
        }

        // Ternarize integer sums: u = a+0.5 >= 1 <=> a>=1 ; u<0 <=> a<=-1.
        char2 o0, o1;
        o0.x = (char)((a00 >= 1) ? 1 : ((a00 <= -1) ? -1 : 0));
        o0.y = (char)((a01 >= 1) ? 1 : ((a01 <= -1) ? -1 : 0));
        o1.x = (char)((a10 >= 1) ? 1 : ((a10 <= -1) ? -1 : 0));
        o1.y = (char)((a11 >= 1) ? 1 : ((a11 <= -1) ? -1 : 0));
        *(char2*)(g_t + (size_t)(bb * 1024 + r0) * 768 + h * 64 + 2 * lane) = o0;
        *(char2*)(g_t + (size_t)(bb * 1024 + r1) * 768 + h * 64 + 2 * lane) = o1;
    }
}

// ---------------------------------------------------------------------------
// GEMM2: Out[m,o] = tern( sum_c T[m,c] * Wproj[o,c] )  (M=8192, N=768, K=768)
// T is ternary int8, W fp32. Same tiling as GEMM1; output float {-1,0,1}.
// ---------------------------------------------------------------------------
__global__ void __launch_bounds__(256) gemm_proj_kernel(const float* __restrict__ W,
                                                        float* __restrict__ Out) {
    __shared__ float As[2][8][132];
    __shared__ float Bs[2][8][132];
    const int tid = threadIdx.x;
    const int tx = tid & 15, ty = tid >> 4;
    const int rowBase = blockIdx.y * 128;
    const int colBase = blockIdx.x * 128;
    const int lr = tid >> 1;
    const int lk = (tid & 1) * 4;

    const float* Bg = W + (size_t)(colBase + lr) * 768 + lk;
    const signed char* Agc = g_t + (size_t)(rowBase + (tid & 127)) * 768;

    float acc[8][8];
#pragma unroll
    for (int i = 0; i < 8; i++)
#pragma unroll
        for (int j = 0; j < 8; j++) acc[i][j] = 0.0f;

    if (tid < 128) {
        const int2 raw = *(const int2*)(Agc);
        const signed char* cp = (const signed char*)&raw;
#pragma unroll
        for (int k2 = 0; k2 < 8; k2++) As[0][k2][tid] = (float)cp[k2];
    }
    {
        const float4 b4 = *(const float4*)Bg;
        Bs[0][lk + 0][lr] = b4.x; Bs[0][lk + 1][lr] = b4.y;
        Bs[0][lk + 2][lr] = b4.z; Bs[0][lk + 3][lr] = b4.w;
    }
    __syncthreads();

    int buf = 0;
    for (int kt = 0; kt < 768; kt += 8) {
        int2 nraw; float4 nb;
        const bool nxt = (kt + 8) < 768;
        if (nxt) {
            if (tid < 128) nraw = *(const int2*)(Agc + kt + 8);
            nb = *(const float4*)(Bg + kt + 8);
        }
#pragma unroll
        for (int kk = 0; kk < 8; kk++) {
            float a[8], b[8];
            *(float4*)(a)     = *(const float4*)&As[buf][kk][ty * 8];
            *(float4*)(a + 4) = *(const float4*)&As[buf][kk][ty * 8 + 4];
            *(float4*)(b)     = *(const float4*)&Bs[buf][kk][tx * 8];
            *(float4*)(b + 4) = *(const float4*)&Bs[buf][kk][tx * 8 + 4];
#pragma unroll
            for (int i = 0; i < 8; i++)
#pragma unroll
                for (int j = 0; j < 8; j++) acc[i][j] = fmaf(a[i], b[j], acc[i][j]);
        }
        if (nxt) {
            const int nb2 = buf ^ 1;
            if (tid < 128) {
                const signed char* cp = (const signed char*)&nraw;
#pragma unroll
                for (int k2 = 0; k2 < 8; k2++) As[nb2][k2][tid] = (float)cp[k2];
            }
            Bs[nb2][lk + 0][lr] = nb.x; Bs[nb2][lk + 1][lr] = nb.y;
            Bs[nb2][lk + 2][lr] = nb.z; Bs[nb2][lk + 3][lr] = nb.w;
        }
        __syncthreads();
        buf ^= 1;
    }

#pragma unroll
    for (int i = 0; i < 8; i++) {
        const int row = rowBase + ty * 8 + i;
        float o[8];
#pragma unroll
        for (int j = 0; j < 8; j++) {
            const float u = acc[i][j] + 0.5f;
            o[j] = (u >= 1.0f) ? 1.0f : ((u < 0.0f) ? -1.0f : 0.0f);
        }
        float* op = Out + (size_t)row * 768 + colBase + tx * 8;
        *(float4*)op       = make_float4(o[0], o[1], o[2], o[3]);
        *(float4*)(op + 4) = make_float4(o[4], o[5], o[6], o[7]);
    }
}

// ---------------------------------------------------------------------------
extern "C" void kernel_launch(void* const* d_in, const int* in_sizes, int n_in,
                              void* d_out, int out_size) {
    (void)in_sizes; (void)n_in; (void)out_size;
    const float* x      = (const float*)d_in[0];  // [8,1024,768]
    const float* w_qkv  = (const float*)d_in[1];  // [2304,768]
    const float* w_proj = (const float*)d_in[2];  // [768,768]
    float* out = (float*)d_out;                   // [8,1024,768]

    cudaFuncSetAttribute(attn_kernel, cudaFuncAttributeMaxDynamicSharedMemorySize, 131072);

    gemm_qkv_kernel<<<dim3(18, 64), 256>>>(x, w_qkv);     // N=2304/128, M=8192/128
    attn_kernel<<<dim3(96, 16), 256, 131072>>>();         // (b*h), 1024/64 row slabs
    gemm_proj_kernel<<<dim3(6, 64), 256>>>(w_proj, out);  // N=768/128, M=8192/128
}